// round 1
// baseline (speedup 1.0000x reference)
#include <cuda_runtime.h>
#include <cuda_bf16.h>

// Problem shapes (fixed by reference)
#define BB  2
#define HH  12
#define NN  2048
#define DD  1024
#define QKD 64
#define HNM 4096

// Scratch (static device allocations are the sanctioned workaround)
__device__ float  g_qbuf[BB * HH * NN * QKD];   // 12.6 MB
__device__ float  g_kbuf[BB * HH * NN * QKD];   // 12.6 MB
__device__ double g_acc;

typedef unsigned long long u64_t;

// ---- packed fp32x2 helpers (sm_103a dual-rate fp32 path) ----
static __device__ __forceinline__ u64_t pack2(float lo, float hi) {
    u64_t r;
    asm("mov.b64 %0, {%1,%2};" : "=l"(r)
        : "r"(__float_as_uint(lo)), "r"(__float_as_uint(hi)));
    return r;
}
static __device__ __forceinline__ u64_t fma2(u64_t a, u64_t b, u64_t c) {
    u64_t d;
    asm("fma.rn.f32x2 %0, %1, %2, %3;" : "=l"(d) : "l"(a), "l"(b), "l"(c));
    return d;
}
static __device__ __forceinline__ float2 unpack2(u64_t v) {
    unsigned lo, hi;
    asm("mov.b64 {%0,%1}, %2;" : "=r"(lo), "=r"(hi) : "l"(v));
    return make_float2(__uint_as_float(lo), __uint_as_float(hi));
}

__global__ void k_init() { g_acc = 0.0; }

// ============================================================================
// Kernel 1: QK projection.  C[r, h*64+kk] = sum_d g[r,d] * W[h,kk,d]
// grid (12 heads, 32 row-tiles, 2 {Wq,Wk}), block 256.
// Tile 128(M) x 64(N=one head) x 8(K); 8x4 outputs/thread, packed f32x2 FMA.
// ============================================================================
__global__ __launch_bounds__(256) void k_proj(const float* __restrict__ g,
                                              const float* __restrict__ Wq,
                                              const float* __restrict__ Wk) {
    __shared__ float As[8][132];   // padded: conflict-free transposed stores
    __shared__ float Bs[8][68];

    const float* W   = (blockIdx.z == 0) ? Wq : Wk;
    float*       out = (blockIdx.z == 0) ? g_qbuf : g_kbuf;
    const int h       = blockIdx.x;
    const int rowBase = blockIdx.y * 128;
    const int t  = threadIdx.x;
    const int tx = t & 15;      // 0..15 over N (4 cols each)
    const int ty = t >> 4;      // 0..15 over M (8 rows each)

    u64_t acc[8][2];
#pragma unroll
    for (int i = 0; i < 8; ++i) { acc[i][0] = 0ull; acc[i][1] = 0ull; }

    const int lr = t >> 1;          // load row
    const int lk = (t & 1) * 4;     // load k offset
    const float* Ap = g + (size_t)(rowBase + lr) * DD + lk;
    const float* Bp = W + ((size_t)h * QKD + lr) * DD + lk;  // deref only if t<128

    for (int kb = 0; kb < DD; kb += 8) {
        float4 av = *(const float4*)(Ap + kb);
        float4 bv = make_float4(0.f, 0.f, 0.f, 0.f);
        if (t < 128) bv = *(const float4*)(Bp + kb);
        __syncthreads();
        As[lk + 0][lr] = av.x; As[lk + 1][lr] = av.y;
        As[lk + 2][lr] = av.z; As[lk + 3][lr] = av.w;
        if (t < 128) {
            Bs[lk + 0][lr] = bv.x; Bs[lk + 1][lr] = bv.y;
            Bs[lk + 2][lr] = bv.z; Bs[lk + 3][lr] = bv.w;
        }
        __syncthreads();
#pragma unroll
        for (int k = 0; k < 8; ++k) {
            float4 a0 = *(const float4*)&As[k][ty * 8];
            float4 a1 = *(const float4*)&As[k][ty * 8 + 4];
            u64_t  b0 = *(const u64_t*)&Bs[k][tx * 4];
            u64_t  b1 = *(const u64_t*)&Bs[k][tx * 4 + 2];
            float a[8] = {a0.x, a0.y, a0.z, a0.w, a1.x, a1.y, a1.z, a1.w};
#pragma unroll
            for (int i = 0; i < 8; ++i) {
                u64_t ai = pack2(a[i], a[i]);
                acc[i][0] = fma2(ai, b0, acc[i][0]);
                acc[i][1] = fma2(ai, b1, acc[i][1]);
            }
        }
    }

    // write to q/k layout [b][h][n][kk]
#pragma unroll
    for (int i = 0; i < 8; ++i) {
        int r = rowBase + ty * 8 + i;
        int b = r >> 11;            // / 2048
        int n = r & (NN - 1);
        float2 v0 = unpack2(acc[i][0]);
        float2 v1 = unpack2(acc[i][1]);
        float4 o  = make_float4(v0.x, v0.y, v1.x, v1.y);
        *(float4*)(out + (((size_t)b * HH + h) * NN + n) * QKD + tx * 4) = o;
    }
}

// ============================================================================
// Kernel 2: streaming attention logsumexp (flash-style, base-2 domain).
// grid (16 q-tiles, 24 = B*H), block 128: one query row per thread,
// q row resident in registers (32x f32x2), key tiles of 128 in SMEM.
// ============================================================================
__global__ __launch_bounds__(128) void k_attn() {
    __shared__ float Ks[128 * 64];   // 32 KB key tile
    __shared__ float red[128];
    const int bh = blockIdx.y;
    const int n0 = blockIdx.x * 128;
    const int t  = threadIdx.x;

    const float* qrow = g_qbuf + ((size_t)bh * NN + n0 + t) * QKD;
    u64_t qv[32];
#pragma unroll
    for (int i = 0; i < 16; ++i) {
        float4 v = *(const float4*)(qrow + i * 4);
        qv[2 * i]     = pack2(v.x, v.y);
        qv[2 * i + 1] = pack2(v.z, v.w);
    }

    const float LOG2E_BETA = 0.125f * 1.4426950408889634f;  // beta * log2(e)
    float m2 = -1e30f, l2 = 0.0f;
    const float* kbase = g_kbuf + (size_t)bh * NN * QKD;

    for (int mt = 0; mt < NN; mt += 128) {
        __syncthreads();
        const float4* src = (const float4*)(kbase + (size_t)mt * QKD);
        float4*       dst = (float4*)Ks;
#pragma unroll
        for (int i = 0; i < 16; ++i) dst[t + i * 128] = src[t + i * 128];
        __syncthreads();
        for (int m = 0; m < 128; ++m) {
            const u64_t* kr = (const u64_t*)(Ks + m * 64);  // broadcast reads
            u64_t a0 = 0ull, a1 = 0ull, a2 = 0ull, a3 = 0ull;
#pragma unroll
            for (int i = 0; i < 32; i += 4) {
                a0 = fma2(qv[i + 0], kr[i + 0], a0);
                a1 = fma2(qv[i + 1], kr[i + 1], a1);
                a2 = fma2(qv[i + 2], kr[i + 2], a2);
                a3 = fma2(qv[i + 3], kr[i + 3], a3);
            }
            float2 s0 = unpack2(a0), s1 = unpack2(a1);
            float2 s2 = unpack2(a2), s3 = unpack2(a3);
            float dot = ((s0.x + s0.y) + (s1.x + s1.y)) +
                        ((s2.x + s2.y) + (s3.x + s3.y));
            float tt = dot * LOG2E_BETA;       // score in log2 domain
            float mn = fmaxf(m2, tt);
            l2 = l2 * exp2f(m2 - mn) + exp2f(tt - mn);
            m2 = mn;
        }
    }
    // natural-log LSE for this query
    float lse = (m2 + log2f(l2)) * 0.69314718055994530942f;
    red[t] = lse;
    __syncthreads();
    for (int s = 64; s > 0; s >>= 1) {
        if (t < s) red[t] += red[t + s];
        __syncthreads();
    }
    if (t == 0) atomicAdd(&g_acc, -8.0 * (double)red[0]);  // -(1/beta) = -8
}

// ============================================================================
// Kernel 3: Hopfield energy.  h = g @ Whn^T (4096x4096x1024), fused
// -0.5*sum(relu(h)^2), no output store. Tile 128x128x8, 8x8/thread, f32x2.
// grid (32, 32), block 256.
// ============================================================================
__global__ __launch_bounds__(256) void k_hop(const float* __restrict__ g,
                                             const float* __restrict__ W) {
    __shared__ float As[8][132];
    __shared__ float Bs[8][132];
    const int rowBase = blockIdx.y * 128;
    const int colBase = blockIdx.x * 128;
    const int t  = threadIdx.x;
    const int tx = t & 15;     // N: 8 cols each (4 packed pairs)
    const int ty = t >> 4;     // M: 8 rows each

    u64_t acc[8][4];
#pragma unroll
    for (int i = 0; i < 8; ++i)
#pragma unroll
        for (int j = 0; j < 4; ++j) acc[i][j] = 0ull;

    const int lr = t >> 1;
    const int lk = (t & 1) * 4;
    const float* Ap = g + (size_t)(rowBase + lr) * DD + lk;
    const float* Bp = W + (size_t)(colBase + lr) * DD + lk;

    for (int kb = 0; kb < DD; kb += 8) {
        float4 av = *(const float4*)(Ap + kb);
        float4 bv = *(const float4*)(Bp + kb);
        __syncthreads();
        As[lk + 0][lr] = av.x; As[lk + 1][lr] = av.y;
        As[lk + 2][lr] = av.z; As[lk + 3][lr] = av.w;
        Bs[lk + 0][lr] = bv.x; Bs[lk + 1][lr] = bv.y;
        Bs[lk + 2][lr] = bv.z; Bs[lk + 3][lr] = bv.w;
        __syncthreads();
#pragma unroll
        for (int k = 0; k < 8; ++k) {
            float4 a0 = *(const float4*)&As[k][ty * 8];
            float4 a1 = *(const float4*)&As[k][ty * 8 + 4];
            const u64_t* bp = (const u64_t*)&Bs[k][tx * 8];
            u64_t b0 = bp[0], b1 = bp[1], b2 = bp[2], b3 = bp[3];
            float a[8] = {a0.x, a0.y, a0.z, a0.w, a1.x, a1.y, a1.z, a1.w};
#pragma unroll
            for (int i = 0; i < 8; ++i) {
                u64_t ai = pack2(a[i], a[i]);
                acc[i][0] = fma2(ai, b0, acc[i][0]);
                acc[i][1] = fma2(ai, b1, acc[i][1]);
                acc[i][2] = fma2(ai, b2, acc[i][2]);
                acc[i][3] = fma2(ai, b3, acc[i][3]);
            }
        }
    }

    float local = 0.0f;
#pragma unroll
    for (int i = 0; i < 8; ++i)
#pragma unroll
        for (int j = 0; j < 4; ++j) {
            float2 v = unpack2(acc[i][j]);
            float r0 = fmaxf(v.x, 0.0f);
            float r1 = fmaxf(v.y, 0.0f);
            local += r0 * r0 + r1 * r1;
        }

    __shared__ float red[256];
    red[t] = local;
    __syncthreads();
    for (int s = 128; s > 0; s >>= 1) {
        if (t < s) red[t] += red[t + s];
        __syncthreads();
    }
    if (t == 0) atomicAdd(&g_acc, -0.5 * (double)red[0]);
}

__global__ void k_fin(float* out) { out[0] = (float)g_acc; }

// ============================================================================
extern "C" void kernel_launch(void* const* d_in, const int* in_sizes, int n_in,
                              void* d_out, int out_size) {
    const float* g   = (const float*)d_in[0];  // [2,2048,1024]
    const float* Wq  = (const float*)d_in[1];  // [12,64,1024]
    const float* Wk  = (const float*)d_in[2];  // [12,64,1024]
    const float* Whn = (const float*)d_in[3];  // [4096,1024]

    k_init<<<1, 1>>>();
    k_proj<<<dim3(12, 32, 2), 256>>>(g, Wq, Wk);
    k_attn<<<dim3(16, 24), 128>>>();
    k_hop<<<dim3(32, 32), 256>>>(g, Whn);
    k_fin<<<1, 1>>>((float*)d_out);
}

// round 3
// speedup vs baseline: 2.1240x; 2.1240x over previous
#include <cuda_runtime.h>
#include <cuda_bf16.h>
#include <cstdint>

// Problem shapes (fixed by reference)
#define BB  2
#define HH  12
#define NN  2048
#define DD  1024
#define QKD 64
#define HNM 4096
#define MROWS (BB * NN)          // 4096

// Scratch (static device allocations are the sanctioned workaround)
__device__ float  g_qbuf[BB * HH * NN * QKD];       // 12.6 MB
__device__ float  g_kbuf[BB * HH * NN * QKD];       // 12.6 MB
__device__ float  gA_frag[MROWS * DD];              // 16 MB  (g, tf32, A-fragment order)
__device__ float  gB_frag[HNM * DD];                // 16 MB  (Whn, tf32, B-fragment order)
__device__ float  gW_frag[2 * HH * QKD * DD];       // 6.3 MB (Wq/Wk, B-fragment order)
__device__ double g_acc;

typedef unsigned long long u64_t;
typedef unsigned int u32_t;

// ============================ small helpers =============================
static __device__ __forceinline__ u64_t pack2(float lo, float hi) {
    u64_t r;
    asm("mov.b64 %0, {%1,%2};" : "=l"(r)
        : "r"(__float_as_uint(lo)), "r"(__float_as_uint(hi)));
    return r;
}
static __device__ __forceinline__ u64_t fma2(u64_t a, u64_t b, u64_t c) {
    u64_t d;
    asm("fma.rn.f32x2 %0, %1, %2, %3;" : "=l"(d) : "l"(a), "l"(b), "l"(c));
    return d;
}
static __device__ __forceinline__ float2 unpack2(u64_t v) {
    unsigned lo, hi;
    asm("mov.b64 {%0,%1}, %2;" : "=r"(lo), "=r"(hi) : "l"(v));
    return make_float2(__uint_as_float(lo), __uint_as_float(hi));
}
static __device__ __forceinline__ float tf32_rna(float x) {
    uint32_t u;
    asm("cvt.rna.tf32.f32 %0, %1;" : "=r"(u) : "f"(x));
    return __uint_as_float(u);
}

// tf32 HMMA: D(16x8,f32) += A(16x8,tf32,row) * B(8x8,tf32,col)
static __device__ __forceinline__ void mma_tf32(float& d0, float& d1, float& d2, float& d3,
                                                u32_t a0, u32_t a1, u32_t a2, u32_t a3,
                                                u32_t b0, u32_t b1) {
    asm volatile(
        "mma.sync.aligned.m16n8k8.row.col.f32.tf32.tf32.f32 "
        "{%0,%1,%2,%3}, {%4,%5,%6,%7}, {%8,%9}, {%0,%1,%2,%3};"
        : "+f"(d0), "+f"(d1), "+f"(d2), "+f"(d3)
        : "r"(a0), "r"(a1), "r"(a2), "r"(a3), "r"(b0), "r"(b1));
}

__global__ void k_init() { g_acc = 0.0; }

// ============================================================================
// Staging: fp32 -> tf32 (RNA) + fragment-major re-layout.
// A-fragment (row-major 16x8 tiles): for element (row, k):
//   mt=row>>4, ks=k>>3, lane=((row&7)<<2)|(k&3), reg=((row>>3)&1)+2*((k>>2)&1)
//   addr = ((mt*(DD/8) + ks)*32 + lane)*4 + reg
// B-fragment (col-major 8x8 tiles): for element (n, k):
//   nt=n>>3, ks=k>>3, lane=((n&7)<<2)|(k&3), reg=(k>>2)&1
//   addr = ((nt*(DD/8) + ks)*32 + lane)*2 + reg
// ============================================================================
__global__ __launch_bounds__(256) void k_stage_a(const float* __restrict__ src) {
    int idx = blockIdx.x * 256 + threadIdx.x;          // over MROWS*DD
    int row = idx >> 10, k = idx & 1023;
    int mt = row >> 4, ri = row & 15;
    int ks = k >> 3;
    int lane = ((ri & 7) << 2) | (k & 3);
    int reg  = ((ri >> 3) & 1) + (((k >> 2) & 1) << 1);
    gA_frag[(((size_t)mt * 128 + ks) * 32 + lane) * 4 + reg] = tf32_rna(src[idx]);
}
__global__ __launch_bounds__(256) void k_stage_b(const float* __restrict__ src) {
    int idx = blockIdx.x * 256 + threadIdx.x;          // over HNM*DD
    int n = idx >> 10, k = idx & 1023;
    int nt = n >> 3;
    int ks = k >> 3;
    int lane = ((n & 7) << 2) | (k & 3);
    int reg  = (k >> 2) & 1;
    gB_frag[(((size_t)nt * 128 + ks) * 32 + lane) * 2 + reg] = tf32_rna(src[idx]);
}
__global__ __launch_bounds__(256) void k_stage_w(const float* __restrict__ Wq,
                                                 const float* __restrict__ Wk) {
    int idx = blockIdx.x * 256 + threadIdx.x;          // over 2*HH*QKD*DD
    int d  = idx & 1023;
    int r  = idx >> 10;          // (z*HH + h)*QKD + kk
    int kk = r & 63;
    int zh = r >> 6;             // z*HH + h
    const float* src = (zh >= HH) ? Wk : Wq;
    int h = (zh >= HH) ? (zh - HH) : zh;
    float v = src[((size_t)h * QKD + kk) * DD + d];
    int nt = kk >> 3;
    int ks = d >> 3;
    int lane = ((kk & 7) << 2) | (d & 3);
    int reg  = (d >> 2) & 1;
    gW_frag[((((size_t)zh * 8 + nt) * 128 + ks) * 32 + lane) * 2 + reg] = tf32_rna(v);
}

// ============================================================================
// Kernel 1: QK projection via tf32 MMA.
// grid (12 heads, 32 row-tiles, 2 {q,k}), block 256 (8 warps).
// CTA tile 128(M) x 64(N). Warp tile 32x32: wm=wid&3, wn=wid>>2.
// ============================================================================
__global__ __launch_bounds__(256) void k_proj() {
    const int t    = threadIdx.x;
    const int lane = t & 31;
    const int wid  = t >> 5;
    const int wm   = wid & 3;          // 0..3
    const int wn   = wid >> 2;         // 0..1
    const int h    = blockIdx.x;
    const int R    = blockIdx.y;
    const int z    = blockIdx.z;

    float acc[2][4][4];
#pragma unroll
    for (int i = 0; i < 2; ++i)
#pragma unroll
        for (int j = 0; j < 4; ++j)
#pragma unroll
            for (int c = 0; c < 4; ++c) acc[i][j][c] = 0.0f;

    const uint4*  Ab = ((const uint4*)gA_frag) + lane;
    const uint2*  Bb = ((const uint2*)gW_frag) + lane;
    size_t aOff[2], bOff[4];
#pragma unroll
    for (int i = 0; i < 2; ++i) aOff[i] = ((size_t)(R * 8 + wm * 2 + i) * 128) * 32;
#pragma unroll
    for (int j = 0; j < 4; ++j)
        bOff[j] = (((size_t)(z * HH + h) * 8 + (wn * 4 + j)) * 128) * 32;

#pragma unroll 2
    for (int ks = 0; ks < 128; ++ks) {
        uint4 a[2]; uint2 b[4];
#pragma unroll
        for (int i = 0; i < 2; ++i) a[i] = Ab[aOff[i] + (size_t)ks * 32];
#pragma unroll
        for (int j = 0; j < 4; ++j) b[j] = Bb[bOff[j] + (size_t)ks * 32];
#pragma unroll
        for (int i = 0; i < 2; ++i)
#pragma unroll
            for (int j = 0; j < 4; ++j)
                mma_tf32(acc[i][j][0], acc[i][j][1], acc[i][j][2], acc[i][j][3],
                         a[i].x, a[i].y, a[i].z, a[i].w, b[j].x, b[j].y);
    }

    float* out = (z == 0) ? g_qbuf : g_kbuf;
#pragma unroll
    for (int i = 0; i < 2; ++i) {
        int row0 = (R * 8 + wm * 2 + i) * 16 + (lane >> 2);
#pragma unroll
        for (int j = 0; j < 4; ++j) {
            int kk = (wn * 4 + j) * 8 + (lane & 3) * 2;
            // row0 and row0+8
            int b0 = row0 >> 11, n0 = row0 & (NN - 1);
            int r1 = row0 + 8;
            int b1 = r1 >> 11,  n1 = r1 & (NN - 1);
            float* p0 = out + (((size_t)b0 * HH + h) * NN + n0) * QKD + kk;
            float* p1 = out + (((size_t)b1 * HH + h) * NN + n1) * QKD + kk;
            *(float2*)p0 = make_float2(acc[i][j][0], acc[i][j][1]);
            *(float2*)p1 = make_float2(acc[i][j][2], acc[i][j][3]);
        }
    }
}

// ============================================================================
// Kernel 2: streaming attention logsumexp (flash-style, base-2 domain).
// 4-key grouping for ILP; 1.25 exp/key.
// ============================================================================
__global__ __launch_bounds__(128) void k_attn() {
    __shared__ float Ks[128 * 64];
    __shared__ float red[128];
    const int bh = blockIdx.y;
    const int n0 = blockIdx.x * 128;
    const int t  = threadIdx.x;

    const float* qrow = g_qbuf + ((size_t)bh * NN + n0 + t) * QKD;
    u64_t qv[32];
#pragma unroll
    for (int i = 0; i < 16; ++i) {
        float4 v = *(const float4*)(qrow + i * 4);
        qv[2 * i]     = pack2(v.x, v.y);
        qv[2 * i + 1] = pack2(v.z, v.w);
    }

    const float LOG2E_BETA = 0.125f * 1.4426950408889634f;
    float m2 = -1e30f, l2 = 0.0f;
    const float* kbase = g_kbuf + (size_t)bh * NN * QKD;

    for (int mt = 0; mt < NN; mt += 128) {
        __syncthreads();
        const float4* src = (const float4*)(kbase + (size_t)mt * QKD);
        float4*       dst = (float4*)Ks;
#pragma unroll
        for (int i = 0; i < 16; ++i) dst[t + i * 128] = src[t + i * 128];
        __syncthreads();
        for (int m = 0; m < 128; m += 4) {
            float tt[4];
#pragma unroll
            for (int j = 0; j < 4; ++j) {
                const u64_t* kr = (const u64_t*)(Ks + (m + j) * 64);
                u64_t a0 = 0ull, a1 = 0ull;
#pragma unroll
                for (int i = 0; i < 32; i += 2) {
                    a0 = fma2(qv[i], kr[i], a0);
                    a1 = fma2(qv[i + 1], kr[i + 1], a1);
                }
                float2 s0 = unpack2(a0), s1 = unpack2(a1);
                tt[j] = ((s0.x + s0.y) + (s1.x + s1.y)) * LOG2E_BETA;
            }
            float mx = fmaxf(fmaxf(tt[0], tt[1]), fmaxf(tt[2], tt[3]));
            float mn = fmaxf(m2, mx);
            l2 = l2 * exp2f(m2 - mn) + exp2f(tt[0] - mn) + exp2f(tt[1] - mn) +
                 exp2f(tt[2] - mn) + exp2f(tt[3] - mn);
            m2 = mn;
        }
    }
    float lse = (m2 + log2f(l2)) * 0.69314718055994530942f;
    red[t] = lse;
    __syncthreads();
    for (int s = 64; s > 0; s >>= 1) {
        if (t < s) red[t] += red[t + s];
        __syncthreads();
    }
    if (t == 0) atomicAdd(&g_acc, -8.0 * (double)red[0]);
}

// ============================================================================
// Kernel 3: Hopfield energy via tf32 MMA, fragments straight from gmem (L2).
// grid (32, 32) CTA tiles of 128x128. Block 256 (8 warps), warp tile 64x32:
// wm=wid>>2 (2), wn=wid&3 (4). 16 mma per k-step-8. Fused relu^2 sum.
// ============================================================================
__global__ __launch_bounds__(256) void k_hop() {
    const int t    = threadIdx.x;
    const int lane = t & 31;
    const int wid  = t >> 5;
    const int wm   = wid >> 2;         // 0..1
    const int wn   = wid & 3;          // 0..3

    float acc[4][4][4];
#pragma unroll
    for (int i = 0; i < 4; ++i)
#pragma unroll
        for (int j = 0; j < 4; ++j)
#pragma unroll
            for (int c = 0; c < 4; ++c) acc[i][j][c] = 0.0f;

    const uint4* Ab = ((const uint4*)gA_frag) + lane;
    const uint2* Bb = ((const uint2*)gB_frag) + lane;
    size_t aOff[4], bOff[4];
#pragma unroll
    for (int i = 0; i < 4; ++i)
        aOff[i] = ((size_t)(blockIdx.y * 8 + wm * 4 + i) * 128) * 32;
#pragma unroll
    for (int j = 0; j < 4; ++j)
        bOff[j] = ((size_t)(blockIdx.x * 16 + wn * 4 + j) * 128) * 32;

#pragma unroll 2
    for (int ks = 0; ks < 128; ++ks) {
        uint4 a[4]; uint2 b[4];
#pragma unroll
        for (int i = 0; i < 4; ++i) a[i] = Ab[aOff[i] + (size_t)ks * 32];
#pragma unroll
        for (int j = 0; j < 4; ++j) b[j] = Bb[bOff[j] + (size_t)ks * 32];
#pragma unroll
        for (int i = 0; i < 4; ++i)
#pragma unroll
            for (int j = 0; j < 4; ++j)
                mma_tf32(acc[i][j][0], acc[i][j][1], acc[i][j][2], acc[i][j][3],
                         a[i].x, a[i].y, a[i].z, a[i].w, b[j].x, b[j].y);
    }

    float local = 0.0f;
#pragma unroll
    for (int i = 0; i < 4; ++i)
#pragma unroll
        for (int j = 0; j < 4; ++j)
#pragma unroll
            for (int c = 0; c < 4; ++c) {
                float v = fmaxf(acc[i][j][c], 0.0f);
                local += v * v;
            }

    __shared__ float red[256];
    red[t] = local;
    __syncthreads();
    for (int s = 128; s > 0; s >>= 1) {
        if (t < s) red[t] += red[t + s];
        __syncthreads();
    }
    if (t == 0) atomicAdd(&g_acc, -0.5 * (double)red[0]);
}

__global__ void k_fin(float* out) { out[0] = (float)g_acc; }

// ============================================================================
extern "C" void kernel_launch(void* const* d_in, const int* in_sizes, int n_in,
                              void* d_out, int out_size) {
    const float* g   = (const float*)d_in[0];  // [2,2048,1024]
    const float* Wq  = (const float*)d_in[1];  // [12,64,1024]
    const float* Wk  = (const float*)d_in[2];  // [12,64,1024]
    const float* Whn = (const float*)d_in[3];  // [4096,1024]

    k_init<<<1, 1>>>();
    k_stage_a<<<(MROWS * DD) / 256, 256>>>(g);
    k_stage_b<<<(HNM * DD) / 256, 256>>>(Whn);
    k_stage_w<<<(2 * HH * QKD * DD) / 256, 256>>>(Wq, Wk);
    k_proj<<<dim3(12, 32, 2), 256>>>();
    k_attn<<<dim3(16, 24), 128>>>();
    k_hop<<<dim3(32, 32), 256>>>();
    k_fin<<<1, 1>>>((float*)d_out);
}

// round 4
// speedup vs baseline: 4.0031x; 1.8847x over previous
#include <cuda_runtime.h>
#include <cuda_bf16.h>
#include <cstdint>

// Problem shapes (fixed by reference)
#define BB  2
#define HH  12
#define NN  2048
#define DD  1024
#define QKD 64
#define HNM 4096
#define MROWS (BB * NN)          // 4096
#define NBH   (BB * HH)          // 24

// Scratch (static device allocations are the sanctioned workaround)
__device__ float  gA_frag[MROWS * DD];              // 16 MB  (g, tf32, A-frag order)
__device__ float  gB_frag[HNM * DD];                // 16 MB  (Whn, tf32, B-frag order)
__device__ float  gW_frag[2 * HH * QKD * DD];       // 6.3 MB (Wq/Wk, B-frag order)
__device__ float  qA_frag[NBH * 128 * 8 * 128];     // 12.6 MB (q, A-frag per bh)
__device__ float  kB_frag[NBH * 256 * 4 * 128];     // 12.6 MB (k, B-frag ks-paired per bh)
__device__ double g_acc;

typedef unsigned int u32_t;

static __device__ __forceinline__ float tf32_rna(float x) {
    uint32_t u;
    asm("cvt.rna.tf32.f32 %0, %1;" : "=r"(u) : "f"(x));
    return __uint_as_float(u);
}

// tf32 HMMA: D(16x8,f32) += A(16x8,tf32,row) * B(8x8,tf32,col)
static __device__ __forceinline__ void mma_tf32(float& d0, float& d1, float& d2, float& d3,
                                                u32_t a0, u32_t a1, u32_t a2, u32_t a3,
                                                u32_t b0, u32_t b1) {
    asm volatile(
        "mma.sync.aligned.m16n8k8.row.col.f32.tf32.tf32.f32 "
        "{%0,%1,%2,%3}, {%4,%5,%6,%7}, {%8,%9}, {%0,%1,%2,%3};"
        : "+f"(d0), "+f"(d1), "+f"(d2), "+f"(d3)
        : "r"(a0), "r"(a1), "r"(a2), "r"(a3), "r"(b0), "r"(b1));
}

__global__ void k_init() { g_acc = 0.0; }

// ============================================================================
// Staging: fp32 -> tf32 (RNA) + fragment-major re-layout.
// A-fragment (16x8 tiles): (row,k) -> lane=((row&7)<<2)|(k&3),
//   reg=((row>>3)&1)+2*((k>>2)&1); addr=((mt*(DD/8)+ks)*32+lane)*4+reg
// B-fragment (8x8 tiles):  (n,k)   -> lane=((n&7)<<2)|(k&3), reg=(k>>2)&1;
//   addr=((nt*(DD/8)+ks)*32+lane)*2+reg
// ============================================================================
__global__ __launch_bounds__(256) void k_stage_a(const float* __restrict__ src) {
    int idx = blockIdx.x * 256 + threadIdx.x;          // over MROWS*DD
    int row = idx >> 10, k = idx & 1023;
    int mt = row >> 4, ri = row & 15;
    int ks = k >> 3;
    int lane = ((ri & 7) << 2) | (k & 3);
    int reg  = ((ri >> 3) & 1) + (((k >> 2) & 1) << 1);
    gA_frag[(((size_t)mt * 128 + ks) * 32 + lane) * 4 + reg] = tf32_rna(src[idx]);
}
__global__ __launch_bounds__(256) void k_stage_b(const float* __restrict__ src) {
    int idx = blockIdx.x * 256 + threadIdx.x;          // over HNM*DD
    int n = idx >> 10, k = idx & 1023;
    int nt = n >> 3;
    int ks = k >> 3;
    int lane = ((n & 7) << 2) | (k & 3);
    int reg  = (k >> 2) & 1;
    gB_frag[(((size_t)nt * 128 + ks) * 32 + lane) * 2 + reg] = tf32_rna(src[idx]);
}
__global__ __launch_bounds__(256) void k_stage_w(const float* __restrict__ Wq,
                                                 const float* __restrict__ Wk) {
    int idx = blockIdx.x * 256 + threadIdx.x;          // over 2*HH*QKD*DD
    int d  = idx & 1023;
    int r  = idx >> 10;
    int kk = r & 63;
    int zh = r >> 6;
    const float* src = (zh >= HH) ? Wk : Wq;
    int h = (zh >= HH) ? (zh - HH) : zh;
    float v = src[((size_t)h * QKD + kk) * DD + d];
    int nt = kk >> 3;
    int ks = d >> 3;
    int lane = ((kk & 7) << 2) | (d & 3);
    int reg  = (d >> 2) & 1;
    gW_frag[((((size_t)zh * 8 + nt) * 128 + ks) * 32 + lane) * 2 + reg] = tf32_rna(v);
}

// ============================================================================
// Kernel 1: QK projection via tf32 MMA, writing q as A-frags and k as
// ks-paired B-frags directly (for the tensorized attention kernel).
// grid (12 heads, 32 row-tiles, 2 {q,k}), block 256 (8 warps).
// CTA tile 128(M) x 64(N). Warp tile 32x32.
// ============================================================================
__global__ __launch_bounds__(256) void k_proj() {
    const int t    = threadIdx.x;
    const int lane = t & 31;
    const int wid  = t >> 5;
    const int wm   = wid & 3;          // 0..3
    const int wn   = wid >> 2;         // 0..1
    const int h    = blockIdx.x;
    const int R    = blockIdx.y;
    const int z    = blockIdx.z;

    float acc[2][4][4];
#pragma unroll
    for (int i = 0; i < 2; ++i)
#pragma unroll
        for (int j = 0; j < 4; ++j)
#pragma unroll
            for (int c = 0; c < 4; ++c) acc[i][j][c] = 0.0f;

    const uint4* Ab = ((const uint4*)gA_frag) + lane;
    const uint2* Bb = ((const uint2*)gW_frag) + lane;
    size_t aOff[2], bOff[4];
#pragma unroll
    for (int i = 0; i < 2; ++i) aOff[i] = ((size_t)(R * 8 + wm * 2 + i) * 128) * 32;
#pragma unroll
    for (int j = 0; j < 4; ++j)
        bOff[j] = (((size_t)(z * HH + h) * 8 + (wn * 4 + j)) * 128) * 32;

#pragma unroll 2
    for (int ks = 0; ks < 128; ++ks) {
        uint4 a[2]; uint2 b[4];
#pragma unroll
        for (int i = 0; i < 2; ++i) a[i] = Ab[aOff[i] + (size_t)ks * 32];
#pragma unroll
        for (int j = 0; j < 4; ++j) b[j] = Bb[bOff[j] + (size_t)ks * 32];
#pragma unroll
        for (int i = 0; i < 2; ++i)
#pragma unroll
            for (int j = 0; j < 4; ++j)
                mma_tf32(acc[i][j][0], acc[i][j][1], acc[i][j][2], acc[i][j][3],
                         a[i].x, a[i].y, a[i].z, a[i].w, b[j].x, b[j].y);
    }

    // Epilogue: scatter into attention fragment layouts.
    // Thread's D values per (i,j): d0=(r,c), d1=(r,c+1), d2=(r+8,c), d3=(r+8,c+1)
    // with r = (lane>>2) within the 16-row tile, c = (wn*4+j)*8 + (lane&3)*2.
    const int lp = ((lane >> 2) << 2) | (((lane & 3) * 2) & 3);  // frag lane'
    const int sreg = ((lane & 3) >> 1);                           // (c>>2)&1
#pragma unroll
    for (int i = 0; i < 2; ++i) {
        int mtg = R * 8 + wm * 2 + i;         // global 16-row tile (0..255)
        int b   = mtg >> 7;                    // batch
        int bh  = b * HH + h;
#pragma unroll
        for (int j = 0; j < 4; ++j) {
            int ks = wn * 4 + j;               // 0..7
            if (z == 0) {
                // q -> A-frag: reg = (ri>>3) + 2*((c>>2)&1); (d0,d2) and (d1,d3)
                // are adjacent in reg -> two float2 stores.
                int mt = mtg & 127;
                float* base = qA_frag + (((size_t)bh * 128 + mt) * 8 + ks) * 128;
                *(float2*)(base + lp * 4 + sreg * 2)       = make_float2(acc[i][j][0], acc[i][j][2]);
                *(float2*)(base + (lp + 1) * 4 + sreg * 2) = make_float2(acc[i][j][1], acc[i][j][3]);
            } else {
                // k -> B-frag ks-paired: [bh][nt][ksp][lane''][slot],
                // slot = (ks&1)*2 + reg. Rows r and r+8 land in nt and nt+1.
                int nt0 = (mtg & 127) * 2;
                int ksp = ks >> 1;
                int slot = (ks & 1) * 2 + sreg;
                float* kb = kB_frag + (((size_t)bh * 256 + nt0) * 4 + ksp) * 128;
                kb[lp * 4 + slot]       = acc[i][j][0];
                kb[(lp + 1) * 4 + slot] = acc[i][j][1];
                kb[512 + lp * 4 + slot]       = acc[i][j][2];   // nt0+1
                kb[512 + (lp + 1) * 4 + slot] = acc[i][j][3];
            }
        }
    }
}

// ============================================================================
// Kernel 2: attention LSE via tf32 MMA, fixed-max exp2 (scores bounded ~±10).
// grid (16 qtiles, 24 bh), block 256 (8 warps). Warp = 16 queries x all keys.
// ============================================================================
__global__ __launch_bounds__(256) void k_attn() {
    const int t    = threadIdx.x;
    const int lane = t & 31;
    const int wid  = t >> 5;
    const int bh   = blockIdx.y;
    const int mt   = blockIdx.x * 8 + wid;    // 16-query tile (0..127)

    // resident q A-frags: 8 ks x uint4
    const uint4* Aq = ((const uint4*)qA_frag) + ((size_t)(bh * 128 + mt) * 8) * 32 + lane;
    uint4 aq[8];
#pragma unroll
    for (int ks = 0; ks < 8; ++ks) aq[ks] = Aq[(size_t)ks * 32];

    const uint4* Kb = ((const uint4*)kB_frag) + ((size_t)bh * 256 * 4) * 32 + lane;

    const float LB = 0.125f * 1.4426950408889634f;   // beta * log2(e)
    float lsum0 = 0.0f, lsum8 = 0.0f;

#pragma unroll 2
    for (int nt = 0; nt < 256; ++nt) {
        uint4 kk0 = Kb[(size_t)(nt * 4 + 0) * 32];
        uint4 kk1 = Kb[(size_t)(nt * 4 + 1) * 32];
        uint4 kk2 = Kb[(size_t)(nt * 4 + 2) * 32];
        uint4 kk3 = Kb[(size_t)(nt * 4 + 3) * 32];
        float d0 = 0.f, d1 = 0.f, d2 = 0.f, d3 = 0.f;
        mma_tf32(d0, d1, d2, d3, aq[0].x, aq[0].y, aq[0].z, aq[0].w, kk0.x, kk0.y);
        mma_tf32(d0, d1, d2, d3, aq[1].x, aq[1].y, aq[1].z, aq[1].w, kk0.z, kk0.w);
        mma_tf32(d0, d1, d2, d3, aq[2].x, aq[2].y, aq[2].z, aq[2].w, kk1.x, kk1.y);
        mma_tf32(d0, d1, d2, d3, aq[3].x, aq[3].y, aq[3].z, aq[3].w, kk1.z, kk1.w);
        mma_tf32(d0, d1, d2, d3, aq[4].x, aq[4].y, aq[4].z, aq[4].w, kk2.x, kk2.y);
        mma_tf32(d0, d1, d2, d3, aq[5].x, aq[5].y, aq[5].z, aq[5].w, kk2.z, kk2.w);
        mma_tf32(d0, d1, d2, d3, aq[6].x, aq[6].y, aq[6].z, aq[6].w, kk3.x, kk3.y);
        mma_tf32(d0, d1, d2, d3, aq[7].x, aq[7].y, aq[7].z, aq[7].w, kk3.z, kk3.w);
        lsum0 += exp2f(d0 * LB) + exp2f(d1 * LB);
        lsum8 += exp2f(d2 * LB) + exp2f(d3 * LB);
    }

    // quad-reduce across the 4 lanes covering each row's key columns
    lsum0 += __shfl_xor_sync(0xFFFFFFFFu, lsum0, 1);
    lsum0 += __shfl_xor_sync(0xFFFFFFFFu, lsum0, 2);
    lsum8 += __shfl_xor_sync(0xFFFFFFFFu, lsum8, 1);
    lsum8 += __shfl_xor_sync(0xFFFFFFFFu, lsum8, 2);

    // per-thread (replicated x4 within quad): log2 of the two row sums
    float v = __log2f(lsum0) + __log2f(lsum8);
    // reduce across the 8 quads (rows) of the warp
    v += __shfl_xor_sync(0xFFFFFFFFu, v, 4);
    v += __shfl_xor_sync(0xFFFFFFFFu, v, 8);
    v += __shfl_xor_sync(0xFFFFFFFFu, v, 16);

    __shared__ float red[8];
    if (lane == 0) red[wid] = v;
    __syncthreads();
    if (t == 0) {
        float s = 0.f;
#pragma unroll
        for (int i = 0; i < 8; ++i) s += red[i];
        // E_attn contribution: -(1/beta) * sum(ln l) = -8*ln2 * sum(log2 l)
        atomicAdd(&g_acc, -8.0 * 0.6931471805599453 * (double)s);
    }
}

// ============================================================================
// Kernel 3: Hopfield energy via tf32 MMA, fragments straight from gmem (L2).
// grid (32, 32) CTA tiles of 128x128. Block 256 (8 warps), warp tile 64x32.
// ============================================================================
__global__ __launch_bounds__(256) void k_hop() {
    const int t    = threadIdx.x;
    const int lane = t & 31;
    const int wid  = t >> 5;
    const int wm   = wid >> 2;         // 0..1
    const int wn   = wid & 3;          // 0..3

    float acc[4][4][4];
#pragma unroll
    for (int i = 0; i < 4; ++i)
#pragma unroll
        for (int j = 0; j < 4; ++j)
#pragma unroll
            for (int c = 0; c < 4; ++c) acc[i][j][c] = 0.0f;

    const uint4* Ab = ((const uint4*)gA_frag) + lane;
    const uint2* Bb = ((const uint2*)gB_frag) + lane;
    size_t aOff[4], bOff[4];
#pragma unroll
    for (int i = 0; i < 4; ++i)
        aOff[i] = ((size_t)(blockIdx.y * 8 + wm * 4 + i) * 128) * 32;
#pragma unroll
    for (int j = 0; j < 4; ++j)
        bOff[j] = ((size_t)(blockIdx.x * 16 + wn * 4 + j) * 128) * 32;

#pragma unroll 2
    for (int ks = 0; ks < 128; ++ks) {
        uint4 a[4]; uint2 b[4];
#pragma unroll
        for (int i = 0; i < 4; ++i) a[i] = Ab[aOff[i] + (size_t)ks * 32];
#pragma unroll
        for (int j = 0; j < 4; ++j) b[j] = Bb[bOff[j] + (size_t)ks * 32];
#pragma unroll
        for (int i = 0; i < 4; ++i)
#pragma unroll
            for (int j = 0; j < 4; ++j)
                mma_tf32(acc[i][j][0], acc[i][j][1], acc[i][j][2], acc[i][j][3],
                         a[i].x, a[i].y, a[i].z, a[i].w, b[j].x, b[j].y);
    }

    float local = 0.0f;
#pragma unroll
    for (int i = 0; i < 4; ++i)
#pragma unroll
        for (int j = 0; j < 4; ++j)
#pragma unroll
            for (int c = 0; c < 4; ++c) {
                float v = fmaxf(acc[i][j][c], 0.0f);
                local += v * v;
            }

    __shared__ float red[256];
    red[t] = local;
    __syncthreads();
    for (int s = 128; s > 0; s >>= 1) {
        if (t < s) red[t] += red[t + s];
        __syncthreads();
    }
    if (t == 0) atomicAdd(&g_acc, -0.5 * (double)red[0]);
}

__global__ void k_fin(float* out) { out[0] = (float)g_acc; }

// ============================================================================
extern "C" void kernel_launch(void* const* d_in, const int* in_sizes, int n_in,
                              void* d_out, int out_size) {
    const float* g   = (const float*)d_in[0];  // [2,2048,1024]
    const float* Wq  = (const float*)d_in[1];  // [12,64,1024]
    const float* Wk  = (const float*)d_in[2];  // [12,64,1024]
    const float* Whn = (const float*)d_in[3];  // [4096,1024]

    k_init<<<1, 1>>>();
    k_stage_a<<<(MROWS * DD) / 256, 256>>>(g);
    k_stage_b<<<(HNM * DD) / 256, 256>>>(Whn);
    k_stage_w<<<(2 * HH * QKD * DD) / 256, 256>>>(Wq, Wk);
    k_proj<<<dim3(12, 32, 2), 256>>>();
    k_attn<<<dim3(16, NBH), 256>>>();
    k_hop<<<dim3(32, 32), 256>>>();
    k_fin<<<1, 1>>>((float*)d_out);
}

// round 6
// speedup vs baseline: 6.3644x; 1.5899x over previous
#include <cuda_runtime.h>
#include <cuda_fp16.h>
#include <cstdint>

// Problem shapes (fixed by reference)
#define BB  2
#define HH  12
#define NN  2048
#define DD  1024
#define QKD 64
#define HNM 4096
#define MROWS (BB * NN)          // 4096
#define NBH   (BB * HH)          // 24
#define KS16  (DD / 16)          // 64 k16-steps

typedef unsigned int u32_t;

// Fragment-major fp16 buffers (uint32 = half2 units)
__device__ u32_t gA_frag[(MROWS / 16) * KS16 * 32 * 4];   // 8 MB  g  A-frags
__device__ u32_t gB_frag[(HNM / 8) * KS16 * 32 * 2];      // 8 MB  Whn B-frags
__device__ u32_t gW_frag[24 * 8 * KS16 * 32 * 2];         // 3 MB  Wq|Wk B-frags
__device__ u32_t qA_frag[NBH * 128 * 4 * 32 * 4];         // 6 MB  q  A-frags
__device__ u32_t kB_frag[NBH * 256 * 4 * 32 * 2];         // 6 MB  k  B-frags
__device__ double g_acc;

static __device__ __forceinline__ u32_t h2(float a, float b) {
    __half2 h = __floats2half2_rn(a, b);
    return *(u32_t*)&h;
}

// fp16 HMMA: D(16x8,f32) += A(16x16,f16,row) * B(16x8,f16,col)
static __device__ __forceinline__ void mma_f16(float& d0, float& d1, float& d2, float& d3,
                                               u32_t a0, u32_t a1, u32_t a2, u32_t a3,
                                               u32_t b0, u32_t b1) {
    asm volatile(
        "mma.sync.aligned.m16n8k16.row.col.f32.f16.f16.f32 "
        "{%0,%1,%2,%3}, {%4,%5,%6,%7}, {%8,%9}, {%0,%1,%2,%3};"
        : "+f"(d0), "+f"(d1), "+f"(d2), "+f"(d3)
        : "r"(a0), "r"(a1), "r"(a2), "r"(a3), "r"(b0), "r"(b1));
}

__global__ void k_init() { g_acc = 0.0; }

// ============================================================================
// Staging: fp32 -> fp16(RN) + fragment-major layout, one half2 per thread.
// A-frag (16x16 tile): (ri,ki): lane=((ri&7)<<2)|((ki>>1)&3),
//   reg=(ri>>3)+2*(ki>>3), half=ki&1. Stored [mt][ks][lane][reg].
// B-frag (8n x 16k tile): (n,ki): lane=((n&7)<<2)|((ki>>1)&3),
//   reg=ki>>3, half=ki&1. Stored [nt][ks][lane][reg].
// ============================================================================
__global__ __launch_bounds__(256) void k_stage_a(const float* __restrict__ src) {
    int idx = blockIdx.x * 256 + threadIdx.x;      // over MROWS*512 pairs
    int row = idx >> 9, k = (idx & 511) * 2;
    float2 v = *(const float2*)(src + (size_t)row * DD + k);
    int mt = row >> 4, ri = row & 15;
    int ks = k >> 4,   ki = k & 15;
    int lane = ((ri & 7) << 2) | ((ki >> 1) & 3);
    int reg  = (ri >> 3) + ((ki >> 3) << 1);
    gA_frag[(((size_t)mt * KS16 + ks) * 32 + lane) * 4 + reg] = h2(v.x, v.y);
}
__global__ __launch_bounds__(256) void k_stage_b(const float* __restrict__ src) {
    int idx = blockIdx.x * 256 + threadIdx.x;      // over HNM*512 pairs
    int n = idx >> 9, k = (idx & 511) * 2;
    float2 v = *(const float2*)(src + (size_t)n * DD + k);
    int nt = n >> 3;
    int ks = k >> 4, ki = k & 15;
    int lane = ((n & 7) << 2) | ((ki >> 1) & 3);
    int reg  = ki >> 3;
    gB_frag[(((size_t)nt * KS16 + ks) * 32 + lane) * 2 + reg] = h2(v.x, v.y);
}
__global__ __launch_bounds__(256) void k_stage_w(const float* __restrict__ Wq,
                                                 const float* __restrict__ Wk) {
    int idx = blockIdx.x * 256 + threadIdx.x;      // over 24*64*512 pairs
    int d = (idx & 511) * 2;
    int r = idx >> 9;
    int kk = r & 63;
    int zh = r >> 6;
    const float* src = (zh >= HH) ? Wk : Wq;
    int hh = (zh >= HH) ? (zh - HH) : zh;
    float2 v = *(const float2*)(src + ((size_t)hh * QKD + kk) * DD + d);
    int nt = kk >> 3;
    int ks = d >> 4, ki = d & 15;
    int lane = ((kk & 7) << 2) | ((ki >> 1) & 3);
    int reg  = ki >> 3;
    gW_frag[((((size_t)zh * 8 + nt) * KS16 + ks) * 32 + lane) * 2 + reg] = h2(v.x, v.y);
}

// ============================================================================
// Kernel 1: QK projection via fp16 MMA; writes q as A-frags, k as B-frags.
// grid (12 heads, 32 row-tiles, 2 {q,k}), block 256 (8 warps), warp 32x32.
// ============================================================================
__global__ __launch_bounds__(256) void k_proj() {
    const int t    = threadIdx.x;
    const int lane = t & 31;
    const int wid  = t >> 5;
    const int wm   = wid & 3;          // 0..3
    const int wn   = wid >> 2;         // 0..1
    const int h    = blockIdx.x;
    const int R    = blockIdx.y;
    const int z    = blockIdx.z;

    float acc[2][4][4];
#pragma unroll
    for (int i = 0; i < 2; ++i)
#pragma unroll
        for (int j = 0; j < 4; ++j)
#pragma unroll
            for (int c = 0; c < 4; ++c) acc[i][j][c] = 0.0f;

    const uint4* Ab = ((const uint4*)gA_frag) + lane;
    const uint2* Bb = ((const uint2*)gW_frag) + lane;
    size_t aOff[2], bOff[4];
#pragma unroll
    for (int i = 0; i < 2; ++i) aOff[i] = ((size_t)(R * 8 + wm * 2 + i) * KS16) * 32;
#pragma unroll
    for (int j = 0; j < 4; ++j)
        bOff[j] = (((size_t)(z * HH + h) * 8 + (wn * 4 + j)) * KS16) * 32;

#pragma unroll 2
    for (int ks = 0; ks < KS16; ++ks) {
        uint4 a[2]; uint2 b[4];
#pragma unroll
        for (int i = 0; i < 2; ++i) a[i] = Ab[aOff[i] + (size_t)ks * 32];
#pragma unroll
        for (int j = 0; j < 4; ++j) b[j] = Bb[bOff[j] + (size_t)ks * 32];
#pragma unroll
        for (int i = 0; i < 2; ++i)
#pragma unroll
            for (int j = 0; j < 4; ++j)
                mma_f16(acc[i][j][0], acc[i][j][1], acc[i][j][2], acc[i][j][3],
                        a[i].x, a[i].y, a[i].z, a[i].w, b[j].x, b[j].y);
    }

    // Epilogue: D lane mapping == fp16 fragment lane mapping (lane'==lane).
    // d0=(r,c) d1=(r,c+1) d2=(r+8,c) d3=(r+8,c+1); r=lane>>2,
    // c=(wn*4+j)*8+(lane&3)*2; ks=c>>4=(wn*4+j)>>1.
#pragma unroll
    for (int i = 0; i < 2; ++i) {
        int mtg = R * 8 + wm * 2 + i;          // 0..255
        int b   = mtg >> 7;
        int bh  = b * HH + h;
#pragma unroll
        for (int j = 0; j < 4; ++j) {
            int ks = (wn * 4 + j) >> 1;
            if (z == 0) {
                int mt = mtg & 127;
                u32_t* base = qA_frag +
                    ((((size_t)bh * 128 + mt) * 4 + ks) * 32 + lane) * 4;
                base[2 * (j & 1)]     = h2(acc[i][j][0], acc[i][j][1]);  // rows r
                base[2 * (j & 1) + 1] = h2(acc[i][j][2], acc[i][j][3]);  // rows r+8
            } else {
                int nt0 = (mtg & 127) * 2;
                u32_t* b0 = kB_frag +
                    ((((size_t)bh * 256 + nt0) * 4 + ks) * 32 + lane) * 2;
                u32_t* b1 = kB_frag +
                    ((((size_t)bh * 256 + nt0 + 1) * 4 + ks) * 32 + lane) * 2;
                b0[j & 1] = h2(acc[i][j][0], acc[i][j][1]);
                b1[j & 1] = h2(acc[i][j][2], acc[i][j][3]);
            }
        }
    }
}

// ============================================================================
// Kernel 2: attention LSE via fp16 MMA, fixed-max exp2 (scores bounded ~±10).
// grid (16 qtiles, 24 bh), block 256 (8 warps). Warp = 16 queries x all keys.
// ============================================================================
__global__ __launch_bounds__(256) void k_attn() {
    const int t    = threadIdx.x;
    const int lane = t & 31;
    const int wid  = t >> 5;
    const int bh   = blockIdx.y;
    const int mt   = blockIdx.x * 8 + wid;     // 0..127

    const uint4* Aq = ((const uint4*)qA_frag) + ((size_t)(bh * 128 + mt) * 4) * 32 + lane;
    uint4 aq[4];
#pragma unroll
    for (int ks = 0; ks < 4; ++ks) aq[ks] = Aq[(size_t)ks * 32];

    const uint2* Kb = ((const uint2*)kB_frag) + ((size_t)bh * 256 * 4) * 32 + lane;

    const float LB = 0.125f * 1.4426950408889634f;   // beta * log2(e)
    float lsum0 = 0.0f, lsum8 = 0.0f;

#pragma unroll 4
    for (int nt = 0; nt < 256; ++nt) {
        uint2 kk0 = Kb[(size_t)(nt * 4 + 0) * 32];
        uint2 kk1 = Kb[(size_t)(nt * 4 + 1) * 32];
        uint2 kk2 = Kb[(size_t)(nt * 4 + 2) * 32];
        uint2 kk3 = Kb[(size_t)(nt * 4 + 3) * 32];
        float d0 = 0.f, d1 = 0.f, d2 = 0.f, d3 = 0.f;
        mma_f16(d0, d1, d2, d3, aq[0].x, aq[0].y, aq[0].z, aq[0].w, kk0.x, kk0.y);
        mma_f16(d0, d1, d2, d3, aq[1].x, aq[1].y, aq[1].z, aq[1].w, kk1.x, kk1.y);
        mma_f16(d0, d1, d2, d3, aq[2].x, aq[2].y, aq[2].z, aq[2].w, kk2.x, kk2.y);
        mma_f16(d0, d1, d2, d3, aq[3].x, aq[3].y, aq[3].z, aq[3].w, kk3.x, kk3.y);
        lsum0 += exp2f(d0 * LB) + exp2f(d1 * LB);
        lsum8 += exp2f(d2 * LB) + exp2f(d3 * LB);
    }

    lsum0 += __shfl_xor_sync(0xFFFFFFFFu, lsum0, 1);
    lsum0 += __shfl_xor_sync(0xFFFFFFFFu, lsum0, 2);
    lsum8 += __shfl_xor_sync(0xFFFFFFFFu, lsum8, 1);
    lsum8 += __shfl_xor_sync(0xFFFFFFFFu, lsum8, 2);

    float v = __log2f(lsum0) + __log2f(lsum8);
    v += __shfl_xor_sync(0xFFFFFFFFu, v, 4);
    v += __shfl_xor_sync(0xFFFFFFFFu, v, 8);
    v += __shfl_xor_sync(0xFFFFFFFFu, v, 16);

    __shared__ float red[8];
    if (lane == 0) red[wid] = v;
    __syncthreads();
    if (t == 0) {
        float s = 0.f;
#pragma unroll
        for (int i = 0; i < 8; ++i) s += red[i];
        atomicAdd(&g_acc, -8.0 * 0.6931471805599453 * (double)s);
    }
}

// ============================================================================
// Kernel 3: Hopfield energy via fp16 MMA, fragments from gmem (L2-resident).
// grid (32, 32) CTA 128x128, block 256 (8 warps), warp tile 64x32.
// ============================================================================
__global__ __launch_bounds__(256) void k_hop() {
    const int t    = threadIdx.x;
    const int lane = t & 31;
    const int wid  = t >> 5;
    const int wm   = wid >> 2;         // 0..1
    const int wn   = wid & 3;          // 0..3

    float acc[4][4][4];
#pragma unroll
    for (int i = 0; i < 4; ++i)
#pragma unroll
        for (int j = 0; j < 4; ++j)
#pragma unroll
            for (int c = 0; c < 4; ++c) acc[i][j][c] = 0.0f;

    const uint4* Ab = ((const uint4*)gA_frag) + lane;
    const uint2* Bb = ((const uint2*)gB_frag) + lane;
    size_t aOff[4], bOff[4];
#pragma unroll
    for (int i = 0; i < 4; ++i)
        aOff[i] = ((size_t)(blockIdx.y * 8 + wm * 4 + i) * KS16) * 32;
#pragma unroll
    for (int j = 0; j < 4; ++j)
        bOff[j] = ((size_t)(blockIdx.x * 16 + wn * 4 + j) * KS16) * 32;

#pragma unroll 2
    for (int ks = 0; ks < KS16; ++ks) {
        uint4 a[4]; uint2 b[4];
#pragma unroll
        for (int i = 0; i < 4; ++i) a[i] = Ab[aOff[i] + (size_t)ks * 32];
#pragma unroll
        for (int j = 0; j < 4; ++j) b[j] = Bb[bOff[j] + (size_t)ks * 32];
#pragma unroll
        for (int i = 0; i < 4; ++i)
#pragma unroll
            for (int j = 0; j < 4; ++j)
                mma_f16(acc[i][j][0], acc[i][j][1], acc[i][j][2], acc[i][j][3],
                        a[i].x, a[i].y, a[i].z, a[i].w, b[j].x, b[j].y);
    }

    float local = 0.0f;
#pragma unroll
    for (int i = 0; i < 4; ++i)
#pragma unroll
        for (int j = 0; j < 4; ++j)
#pragma unroll
            for (int c = 0; c < 4; ++c) {
                float v = fmaxf(acc[i][j][c], 0.0f);
                local += v * v;
            }

    __shared__ float red[256];
    red[t] = local;
    __syncthreads();
    for (int s = 128; s > 0; s >>= 1) {
        if (t < s) red[t] += red[t + s];
        __syncthreads();
    }
    if (t == 0) atomicAdd(&g_acc, -0.5 * (double)red[0]);
}

__global__ void k_fin(float* out) { out[0] = (float)g_acc; }

// ============================================================================
extern "C" void kernel_launch(void* const* d_in, const int* in_sizes, int n_in,
                              void* d_out, int out_size) {
    const float* g   = (const float*)d_in[0];  // [2,2048,1024]
    const float* Wq  = (const float*)d_in[1];  // [12,64,1024]
    const float* Wk  = (const float*)d_in[2];  // [12,64,1024]
    const float* Whn = (const float*)d_in[3];  // [4096,1024]

    k_init<<<1, 1>>>();
    k_stage_a<<<(MROWS * DD / 2) / 256, 256>>>(g);
    k_stage_b<<<(HNM * DD / 2) / 256, 256>>>(Whn);
    k_stage_w<<<(2 * HH * QKD * DD / 2) / 256, 256>>>(Wq, Wk);
    k_proj<<<dim3(12, 32, 2), 256>>>();
    k_attn<<<dim3(16, NBH), 256>>>();
    k_hop<<<dim3(32, 32), 256>>>();
    k_fin<<<1, 1>>>((float*)d_out);
}